// round 1
// baseline (speedup 1.0000x reference)
#include <cuda_runtime.h>

#define S 512
#define D 512
#define H 8
#define HD 64
#define NE 1024

// ---- scratch (no allocations allowed) ----
__device__ float g_q[S * D];
__device__ float g_k[S * D];
__device__ float g_v[S * D];
__device__ float g_rkt[NE * D];
__device__ float g_rqt[NE * D];
__device__ float g_ctx[S * D];

// ============================================================
// C[M,N] = A[M,K] @ W[N,K]^T + bias[N]   (torch Linear layout)
// 64x64 tile, K-step 16, 16x16 threads, 4x4 per thread.
// M,N multiples of 64; K multiple of 16.
// ============================================================
__global__ void gemm_bias_kernel(const float* __restrict__ A,
                                 const float* __restrict__ W,
                                 const float* __restrict__ bias,
                                 float* __restrict__ C,
                                 int M, int N, int K) {
    __shared__ float As[16][64];
    __shared__ float Bs[16][64];
    const int tx = threadIdx.x, ty = threadIdx.y;
    const int tid = ty * 16 + tx;
    const int m0 = blockIdx.y * 64, n0 = blockIdx.x * 64;

    float acc[4][4];
#pragma unroll
    for (int i = 0; i < 4; i++)
#pragma unroll
        for (int j = 0; j < 4; j++) acc[i][j] = 0.0f;

    const int lm = tid >> 2;        // 0..63
    const int lk = (tid & 3) * 4;   // 0,4,8,12

    for (int k0 = 0; k0 < K; k0 += 16) {
        float4 av = *(const float4*)(A + (size_t)(m0 + lm) * K + k0 + lk);
        float4 wv = *(const float4*)(W + (size_t)(n0 + lm) * K + k0 + lk);
        As[lk + 0][lm] = av.x; As[lk + 1][lm] = av.y;
        As[lk + 2][lm] = av.z; As[lk + 3][lm] = av.w;
        Bs[lk + 0][lm] = wv.x; Bs[lk + 1][lm] = wv.y;
        Bs[lk + 2][lm] = wv.z; Bs[lk + 3][lm] = wv.w;
        __syncthreads();
#pragma unroll
        for (int kk = 0; kk < 16; kk++) {
            float a[4], b[4];
#pragma unroll
            for (int i = 0; i < 4; i++) a[i] = As[kk][ty + 16 * i];
#pragma unroll
            for (int j = 0; j < 4; j++) b[j] = Bs[kk][tx + 16 * j];
#pragma unroll
            for (int i = 0; i < 4; i++)
#pragma unroll
                for (int j = 0; j < 4; j++) acc[i][j] += a[i] * b[j];
        }
        __syncthreads();
    }

#pragma unroll
    for (int i = 0; i < 4; i++) {
        const int m = m0 + ty + 16 * i;
#pragma unroll
        for (int j = 0; j < 4; j++) {
            const int n = n0 + tx + 16 * j;
            C[(size_t)m * N + n] = acc[i][j] + bias[n];
        }
    }
}

// ============================================================
// scores + softmax, fused.
// block = (h=blockIdx.y, i=blockIdx.x), 512 threads (one per j).
// score[h,i,j] = ( q[h,i]·k[h,j] + q[h,i]·rkt[j-i+512,h]
//                + rqt[j-i+512,h]·k[h,j] ) / 8
// then softmax over j, written to attn[h,i,j].
// ============================================================
__global__ void scores_softmax_kernel(const float* __restrict__ qf,
                                      const float* __restrict__ kf,
                                      const float* __restrict__ rkt,
                                      const float* __restrict__ rqt,
                                      float* __restrict__ attn) {
    const int i = blockIdx.x, h = blockIdx.y;
    const int j = threadIdx.x;

    __shared__ float q_s[HD];
    __shared__ float red[16];
    __shared__ float bc;

    if (j < HD) q_s[j] = qf[(size_t)i * D + h * HD + j];
    __syncthreads();

    int e = j - i + NE / 2;
    e = max(0, min(NE - 1, e));

    const float4* kr = (const float4*)(kf  + (size_t)j * D + h * HD);
    const float4* rk = (const float4*)(rkt + (size_t)e * D + h * HD);
    const float4* rq = (const float4*)(rqt + (size_t)e * D + h * HD);
    const float4* qv = (const float4*)q_s;

    float s1 = 0.f, s2 = 0.f, s3 = 0.f;
#pragma unroll
    for (int c = 0; c < HD / 4; c++) {
        float4 kc = kr[c], rc = rk[c], qc = qv[c], rqc = rq[c];
        s1 += qc.x * kc.x + qc.y * kc.y + qc.z * kc.z + qc.w * kc.w;
        s2 += qc.x * rc.x + qc.y * rc.y + qc.z * rc.z + qc.w * rc.w;
        s3 += rqc.x * kc.x + rqc.y * kc.y + rqc.z * kc.z + rqc.w * kc.w;
    }
    const float sc = (s1 + s2 + s3) * 0.125f;  // 1/sqrt(64)

    const int warp = j >> 5, lane = j & 31;

    // block max
    float v = sc;
#pragma unroll
    for (int o = 16; o; o >>= 1) v = fmaxf(v, __shfl_xor_sync(0xffffffffu, v, o));
    if (lane == 0) red[warp] = v;
    __syncthreads();
    if (warp == 0) {
        float w = (lane < 16) ? red[lane] : -1e30f;
#pragma unroll
        for (int o = 8; o; o >>= 1) w = fmaxf(w, __shfl_xor_sync(0xffffffffu, w, o));
        if (lane == 0) bc = w;
    }
    __syncthreads();
    const float mx = bc;

    const float ex = __expf(sc - mx);

    // block sum
    v = ex;
#pragma unroll
    for (int o = 16; o; o >>= 1) v += __shfl_xor_sync(0xffffffffu, v, o);
    if (lane == 0) red[warp] = v;
    __syncthreads();
    if (warp == 0) {
        float w = (lane < 16) ? red[lane] : 0.f;
#pragma unroll
        for (int o = 8; o; o >>= 1) w += __shfl_xor_sync(0xffffffffu, w, o);
        if (lane == 0) bc = w;
    }
    __syncthreads();

    attn[((size_t)h * S + i) * S + j] = ex / bc;
}

// ============================================================
// ctx[i, h*64+c] = sum_j attn[h,i,j] * v[j, h*64+c]
// block per (i,h), 64 threads over c.
// ============================================================
__global__ void ctx_kernel(const float* __restrict__ attn,
                           const float* __restrict__ vf,
                           float* __restrict__ ctx) {
    const int i = blockIdx.x, h = blockIdx.y;
    const int c = threadIdx.x;  // 0..63

    __shared__ float arow[S];
    for (int j = c; j < S; j += HD)
        arow[j] = attn[((size_t)h * S + i) * S + j];
    __syncthreads();

    float acc = 0.f;
#pragma unroll 8
    for (int j = 0; j < S; j++)
        acc += arow[j] * vf[(size_t)j * D + h * HD + c];

    ctx[(size_t)i * D + h * HD + c] = acc;
}

extern "C" void kernel_launch(void* const* d_in, const int* in_sizes, int n_in,
                              void* d_out, int out_size) {
    const float* hs  = (const float*)d_in[0];
    const float* emb = (const float*)d_in[1];
    const float* wq  = (const float*)d_in[2];
    const float* bq  = (const float*)d_in[3];
    const float* wk  = (const float*)d_in[4];
    const float* bk  = (const float*)d_in[5];
    const float* wv  = (const float*)d_in[6];
    const float* bv  = (const float*)d_in[7];
    const float* wrk = (const float*)d_in[8];
    const float* brk = (const float*)d_in[9];
    const float* wrq = (const float*)d_in[10];
    const float* brq = (const float*)d_in[11];
    const float* wo  = (const float*)d_in[12];
    const float* bo  = (const float*)d_in[13];

    float* out  = (float*)d_out;          // [1,512,512]
    float* attn = out + (size_t)S * D;    // [1,8,512,512] follows

    float *q, *k, *v, *rkt, *rqt, *ctx;
    cudaGetSymbolAddress((void**)&q,   g_q);
    cudaGetSymbolAddress((void**)&k,   g_k);
    cudaGetSymbolAddress((void**)&v,   g_v);
    cudaGetSymbolAddress((void**)&rkt, g_rkt);
    cudaGetSymbolAddress((void**)&rqt, g_rqt);
    cudaGetSymbolAddress((void**)&ctx, g_ctx);

    const dim3 tb(16, 16);
    // q/k/v projections: [512,512] @ [512,512]^T
    gemm_bias_kernel<<<dim3(D / 64, S / 64), tb>>>(hs, wq, bq, q, S, D, D);
    gemm_bias_kernel<<<dim3(D / 64, S / 64), tb>>>(hs, wk, bk, k, S, D, D);
    gemm_bias_kernel<<<dim3(D / 64, S / 64), tb>>>(hs, wv, bv, v, S, D, D);
    // relative tables: [1024,512] @ [512,512]^T  (replaces the huge rel_emb GEMMs)
    gemm_bias_kernel<<<dim3(D / 64, NE / 64), tb>>>(emb, wrk, brk, rkt, NE, D, D);
    gemm_bias_kernel<<<dim3(D / 64, NE / 64), tb>>>(emb, wrq, brq, rqt, NE, D, D);

    // fused scores + softmax -> attn (directly into d_out region)
    scores_softmax_kernel<<<dim3(S, H), S>>>(q, k, rkt, rqt, attn);

    // ctx = attn @ v (per head)
    ctx_kernel<<<dim3(S, H), HD>>>(attn, v, ctx);

    // output projection -> out
    gemm_bias_kernel<<<dim3(D / 64, S / 64), tb>>>(ctx, wo, bo, out, S, D, D);
}

// round 2
// speedup vs baseline: 2.2102x; 2.2102x over previous
#include <cuda_runtime.h>

#define S 512
#define D 512
#define H 8
#define HD 64
#define NE 1024

// ---- scratch (no allocations allowed) ----
__device__ float g_q[S * D];
__device__ float g_k[S * D];
__device__ float g_v[S * D];
__device__ float g_rkt[NE * D];
__device__ float g_rqt[NE * D];
__device__ float g_ctx[S * D];
__device__ float g_A[H * S * S];    // q·k content scores
__device__ float g_B[H * S * NE];   // q·rkt  [h,i,e]
__device__ float g_C[H * NE * S];   // rqt·k  [h,e,j]

// ============================================================
// Fused projection GEMM: z selects which of the 5 projections.
// C[M,512] = A[M,512] @ W[512,512]^T + bias. 64x64 tile.
// ============================================================
__global__ void proj_kernel(const float* __restrict__ hs, const float* __restrict__ emb,
                            const float* __restrict__ wq, const float* __restrict__ bq,
                            const float* __restrict__ wk, const float* __restrict__ bk,
                            const float* __restrict__ wv, const float* __restrict__ bv,
                            const float* __restrict__ wrk, const float* __restrict__ brk,
                            const float* __restrict__ wrq, const float* __restrict__ brq,
                            float* __restrict__ q, float* __restrict__ k, float* __restrict__ v,
                            float* __restrict__ rkt, float* __restrict__ rqt) {
    const float *A, *W, *bias; float* C; int M;
    switch (blockIdx.z) {
        case 0: A = hs;  W = wq;  bias = bq;  C = q;   M = S;  break;
        case 1: A = hs;  W = wk;  bias = bk;  C = k;   M = S;  break;
        case 2: A = hs;  W = wv;  bias = bv;  C = v;   M = S;  break;
        case 3: A = emb; W = wrk; bias = brk; C = rkt; M = NE; break;
        default:A = emb; W = wrq; bias = brq; C = rqt; M = NE; break;
    }
    const int m0 = blockIdx.y * 64, n0 = blockIdx.x * 64;
    if (m0 >= M) return;

    __shared__ float As[16][64];
    __shared__ float Bs[16][64];
    const int tx = threadIdx.x, ty = threadIdx.y;
    const int tid = ty * 16 + tx;

    float acc[4][4];
#pragma unroll
    for (int i = 0; i < 4; i++)
#pragma unroll
        for (int j = 0; j < 4; j++) acc[i][j] = 0.0f;

    const int lm = tid >> 2;
    const int lk = (tid & 3) * 4;

    for (int k0 = 0; k0 < D; k0 += 16) {
        float4 av = *(const float4*)(A + (size_t)(m0 + lm) * D + k0 + lk);
        float4 wv4 = *(const float4*)(W + (size_t)(n0 + lm) * D + k0 + lk);
        As[lk + 0][lm] = av.x;  As[lk + 1][lm] = av.y;
        As[lk + 2][lm] = av.z;  As[lk + 3][lm] = av.w;
        Bs[lk + 0][lm] = wv4.x; Bs[lk + 1][lm] = wv4.y;
        Bs[lk + 2][lm] = wv4.z; Bs[lk + 3][lm] = wv4.w;
        __syncthreads();
#pragma unroll
        for (int kk = 0; kk < 16; kk++) {
            float a[4], b[4];
#pragma unroll
            for (int i = 0; i < 4; i++) a[i] = As[kk][ty + 16 * i];
#pragma unroll
            for (int j = 0; j < 4; j++) b[j] = Bs[kk][tx + 16 * j];
#pragma unroll
            for (int i = 0; i < 4; i++)
#pragma unroll
                for (int j = 0; j < 4; j++) acc[i][j] += a[i] * b[j];
        }
        __syncthreads();
    }

#pragma unroll
    for (int i = 0; i < 4; i++) {
        const int m = m0 + ty + 16 * i;
#pragma unroll
        for (int j = 0; j < 4; j++) {
            const int n = n0 + tx + 16 * j;
            C[(size_t)m * D + n] = acc[i][j] + bias[n];
        }
    }
}

// ============================================================
// Head-batched GEMM. z = batch index; per-z element offsets.
// B_NK=true : C[m,n] = sum_k A[m*lda+k] * B[n*ldb+k]  (+bias)
// B_NK=false: C[m,n] = sum_k A[m*lda+k] * B[k*ldb+n]  (+bias)
// 64x64 tile, 256 threads, K multiple of 16.
// ============================================================
template <bool B_NK>
__global__ void gemm_batched_kernel(const float* __restrict__ A, int lda, int aOff,
                                    const float* __restrict__ B, int ldb, int bOff,
                                    const float* __restrict__ bias,
                                    float* __restrict__ C, int ldc, int cOff,
                                    int K) {
    const int z = blockIdx.z;
    A += (size_t)z * aOff;
    B += (size_t)z * bOff;
    C += (size_t)z * cOff;

    __shared__ float As[16][64];
    __shared__ float Bs[16][64];
    const int tx = threadIdx.x, ty = threadIdx.y;
    const int tid = ty * 16 + tx;
    const int m0 = blockIdx.y * 64, n0 = blockIdx.x * 64;

    float acc[4][4];
#pragma unroll
    for (int i = 0; i < 4; i++)
#pragma unroll
        for (int j = 0; j < 4; j++) acc[i][j] = 0.0f;

    const int lm = tid >> 2;        // 0..63
    const int lk = (tid & 3) * 4;   // 0,4,8,12
    const int lk2 = tid >> 4;       // 0..15
    const int ln4 = (tid & 15) * 4; // 0..60

    for (int k0 = 0; k0 < K; k0 += 16) {
        float4 av = *(const float4*)(A + (size_t)(m0 + lm) * lda + k0 + lk);
        As[lk + 0][lm] = av.x; As[lk + 1][lm] = av.y;
        As[lk + 2][lm] = av.z; As[lk + 3][lm] = av.w;
        if (B_NK) {
            float4 bv = *(const float4*)(B + (size_t)(n0 + lm) * ldb + k0 + lk);
            Bs[lk + 0][lm] = bv.x; Bs[lk + 1][lm] = bv.y;
            Bs[lk + 2][lm] = bv.z; Bs[lk + 3][lm] = bv.w;
        } else {
            float4 bv = *(const float4*)(B + (size_t)(k0 + lk2) * ldb + n0 + ln4);
            *(float4*)&Bs[lk2][ln4] = bv;
        }
        __syncthreads();
#pragma unroll
        for (int kk = 0; kk < 16; kk++) {
            float a[4], b[4];
#pragma unroll
            for (int i = 0; i < 4; i++) a[i] = As[kk][ty + 16 * i];
#pragma unroll
            for (int j = 0; j < 4; j++) b[j] = Bs[kk][tx + 16 * j];
#pragma unroll
            for (int i = 0; i < 4; i++)
#pragma unroll
                for (int j = 0; j < 4; j++) acc[i][j] += a[i] * b[j];
        }
        __syncthreads();
    }

#pragma unroll
    for (int i = 0; i < 4; i++) {
        const int m = m0 + ty + 16 * i;
#pragma unroll
        for (int j = 0; j < 4; j++) {
            const int n = n0 + tx + 16 * j;
            float r = acc[i][j];
            if (bias) r += bias[n];
            C[(size_t)m * ldc + n] = r;
        }
    }
}

// ============================================================
// Gather the three score terms along e = j-i+512, softmax over j.
// block = (i, h), 512 threads (one per j).
// ============================================================
__global__ void softmax_gather_kernel(const float* __restrict__ Asc,
                                      const float* __restrict__ Bm,
                                      const float* __restrict__ Cm,
                                      float* __restrict__ attn) {
    const int i = blockIdx.x, h = blockIdx.y;
    const int j = threadIdx.x;
    const int e = j - i + NE / 2;   // always in [1, 1023]

    __shared__ float red[16];
    __shared__ float bc;

    float sc = (Asc[((size_t)h * S + i) * S + j]
              + Bm[((size_t)h * S + i) * NE + e]
              + Cm[((size_t)h * NE + e) * S + j]) * 0.125f;

    const int warp = j >> 5, lane = j & 31;

    float vmax = sc;
#pragma unroll
    for (int o = 16; o; o >>= 1) vmax = fmaxf(vmax, __shfl_xor_sync(0xffffffffu, vmax, o));
    if (lane == 0) red[warp] = vmax;
    __syncthreads();
    if (warp == 0) {
        float w = (lane < 16) ? red[lane] : -1e30f;
#pragma unroll
        for (int o = 8; o; o >>= 1) w = fmaxf(w, __shfl_xor_sync(0xffffffffu, w, o));
        if (lane == 0) bc = w;
    }
    __syncthreads();
    const float ex = __expf(sc - bc);

    float vsum = ex;
#pragma unroll
    for (int o = 16; o; o >>= 1) vsum += __shfl_xor_sync(0xffffffffu, vsum, o);
    if (lane == 0) red[warp] = vsum;
    __syncthreads();
    if (warp == 0) {
        float w = (lane < 16) ? red[lane] : 0.f;
#pragma unroll
        for (int o = 8; o; o >>= 1) w += __shfl_xor_sync(0xffffffffu, w, o);
        if (lane == 0) bc = w;
    }
    __syncthreads();

    attn[((size_t)h * S + i) * S + j] = ex / bc;
}

extern "C" void kernel_launch(void* const* d_in, const int* in_sizes, int n_in,
                              void* d_out, int out_size) {
    const float* hs  = (const float*)d_in[0];
    const float* emb = (const float*)d_in[1];
    const float* wq  = (const float*)d_in[2];
    const float* bq  = (const float*)d_in[3];
    const float* wk  = (const float*)d_in[4];
    const float* bk  = (const float*)d_in[5];
    const float* wv  = (const float*)d_in[6];
    const float* bv  = (const float*)d_in[7];
    const float* wrk = (const float*)d_in[8];
    const float* brk = (const float*)d_in[9];
    const float* wrq = (const float*)d_in[10];
    const float* brq = (const float*)d_in[11];
    const float* wo  = (const float*)d_in[12];
    const float* bo  = (const float*)d_in[13];

    float* out  = (float*)d_out;          // [1,512,512]
    float* attn = out + (size_t)S * D;    // [1,8,512,512]

    float *q, *k, *v, *rkt, *rqt, *ctx, *Asc, *Bm, *Cm;
    cudaGetSymbolAddress((void**)&q,   g_q);
    cudaGetSymbolAddress((void**)&k,   g_k);
    cudaGetSymbolAddress((void**)&v,   g_v);
    cudaGetSymbolAddress((void**)&rkt, g_rkt);
    cudaGetSymbolAddress((void**)&rqt, g_rqt);
    cudaGetSymbolAddress((void**)&ctx, g_ctx);
    cudaGetSymbolAddress((void**)&Asc, g_A);
    cudaGetSymbolAddress((void**)&Bm,  g_B);
    cudaGetSymbolAddress((void**)&Cm,  g_C);

    const dim3 tb(16, 16);

    // 1. all 5 projections in one launch (448 active blocks)
    proj_kernel<<<dim3(D / 64, NE / 64, 5), tb>>>(hs, emb, wq, bq, wk, bk, wv, bv,
                                                  wrk, brk, wrq, brq,
                                                  q, k, v, rkt, rqt);

    // 2. content scores: A[h,i,j] = q_h @ k_h^T   (K=64, 512 blocks)
    gemm_batched_kernel<true><<<dim3(S / 64, S / 64, H), tb>>>(
        q, D, HD, k, D, HD, nullptr, Asc, S, S * S, HD);

    // 3. B[h,i,e] = q_h @ rkt_h^T   (K=64, 1024 blocks)
    gemm_batched_kernel<true><<<dim3(NE / 64, S / 64, H), tb>>>(
        q, D, HD, rkt, D, HD, nullptr, Bm, NE, S * NE, HD);

    // 4. C[h,e,j] = rqt_h @ k_h^T   (K=64, 1024 blocks)
    gemm_batched_kernel<true><<<dim3(S / 64, NE / 64, H), tb>>>(
        rqt, D, HD, k, D, HD, nullptr, Cm, S, NE * S, HD);

    // 5. gather diagonal terms + softmax -> attn (into d_out region)
    softmax_gather_kernel<<<dim3(S, H), S>>>(Asc, Bm, Cm, attn);

    // 6. ctx_h = attn_h @ v_h   (B in [K,N] layout, 64 blocks)
    gemm_batched_kernel<false><<<dim3(1, S / 64, H), tb>>>(
        attn, S, S * S, v, D, HD, nullptr, ctx, D, HD, S);

    // 7. out = ctx @ wo^T + bo
    gemm_batched_kernel<true><<<dim3(D / 64, S / 64, 1), tb>>>(
        ctx, D, 0, wo, D, 0, bo, out, D, 0, D);
}

// round 3
// speedup vs baseline: 3.0201x; 1.3664x over previous
#include <cuda_runtime.h>

#define S 512
#define D 512
#define H 8
#define HD 64
#define NE 1024

// ---- scratch ----
__device__ float g_q[S * D];
__device__ float g_k[S * D];
__device__ float g_v[S * D];
__device__ float g_rkt[NE * D];
__device__ float g_rqt[NE * D];
__device__ float g_ctx[S * D];
__device__ float g_A[H * S * S];    // q·k        [h,i,j]
__device__ float g_B[H * S * NE];   // q·rkt      [h,i,e]
__device__ float g_C[H * NE * S];   // rqt·k      [h,e,j]

// ============================================================
// proj: fused 5-way projection. 128x128 tile, 256 thr, 8x8/thr,
// double-buffered smem. C[M,512] = A[M,512] @ W[512,512]^T + b
// ============================================================
__global__ __launch_bounds__(256) void proj_kernel(
        const float* __restrict__ hs, const float* __restrict__ emb,
        const float* __restrict__ wq, const float* __restrict__ bq,
        const float* __restrict__ wk, const float* __restrict__ bk,
        const float* __restrict__ wv, const float* __restrict__ bv,
        const float* __restrict__ wrk, const float* __restrict__ brk,
        const float* __restrict__ wrq, const float* __restrict__ brq,
        float* __restrict__ q, float* __restrict__ k, float* __restrict__ v,
        float* __restrict__ rkt, float* __restrict__ rqt) {
    const float *A, *W, *bias; float* Cm; int M;
    switch (blockIdx.z) {
        case 0: A = hs;  W = wq;  bias = bq;  Cm = q;   M = S;  break;
        case 1: A = hs;  W = wk;  bias = bk;  Cm = k;   M = S;  break;
        case 2: A = hs;  W = wv;  bias = bv;  Cm = v;   M = S;  break;
        case 3: A = emb; W = wrk; bias = brk; Cm = rkt; M = NE; break;
        default:A = emb; W = wrq; bias = brq; Cm = rqt; M = NE; break;
    }
    const int m0 = blockIdx.y * 128, n0 = blockIdx.x * 128;
    if (m0 >= M) return;

    __shared__ float As[2][16][132];
    __shared__ float Bs[2][16][132];

    const int tid = threadIdx.x;
    const int r0 = tid >> 2;          // 0..63
    const int c4 = (tid & 3) * 4;     // 0,4,8,12
    const int ty = tid >> 4, tx = tid & 15;

    const float* Ar0 = A + (size_t)(m0 + r0) * D + c4;
    const float* Ar1 = A + (size_t)(m0 + 64 + r0) * D + c4;
    const float* Wr0 = W + (size_t)(n0 + r0) * D + c4;
    const float* Wr1 = W + (size_t)(n0 + 64 + r0) * D + c4;

    float4 pa0, pa1, pb0, pb1;

#define PROJ_LOAD(K0) do { \
        pa0 = *(const float4*)(Ar0 + (K0)); \
        pa1 = *(const float4*)(Ar1 + (K0)); \
        pb0 = *(const float4*)(Wr0 + (K0)); \
        pb1 = *(const float4*)(Wr1 + (K0)); } while (0)

#define PROJ_STORE(BUF) do { \
        As[BUF][c4 + 0][r0] = pa0.x; As[BUF][c4 + 1][r0] = pa0.y; \
        As[BUF][c4 + 2][r0] = pa0.z; As[BUF][c4 + 3][r0] = pa0.w; \
        As[BUF][c4 + 0][64 + r0] = pa1.x; As[BUF][c4 + 1][64 + r0] = pa1.y; \
        As[BUF][c4 + 2][64 + r0] = pa1.z; As[BUF][c4 + 3][64 + r0] = pa1.w; \
        Bs[BUF][c4 + 0][r0] = pb0.x; Bs[BUF][c4 + 1][r0] = pb0.y; \
        Bs[BUF][c4 + 2][r0] = pb0.z; Bs[BUF][c4 + 3][r0] = pb0.w; \
        Bs[BUF][c4 + 0][64 + r0] = pb1.x; Bs[BUF][c4 + 1][64 + r0] = pb1.y; \
        Bs[BUF][c4 + 2][64 + r0] = pb1.z; Bs[BUF][c4 + 3][64 + r0] = pb1.w; } while (0)

    float acc[8][8];
#pragma unroll
    for (int i = 0; i < 8; i++)
#pragma unroll
        for (int j = 0; j < 8; j++) acc[i][j] = 0.f;

    PROJ_LOAD(0);
    PROJ_STORE(0);
    __syncthreads();

    int buf = 0;
    for (int k0 = 0; k0 < D; k0 += 16) {
        const bool more = (k0 + 16 < D);
        if (more) PROJ_LOAD(k0 + 16);
#pragma unroll
        for (int kk = 0; kk < 16; kk++) {
            float4 a0 = *(const float4*)&As[buf][kk][ty * 4];
            float4 a1 = *(const float4*)&As[buf][kk][64 + ty * 4];
            float4 b0 = *(const float4*)&Bs[buf][kk][tx * 4];
            float4 b1 = *(const float4*)&Bs[buf][kk][64 + tx * 4];
            float a[8] = {a0.x, a0.y, a0.z, a0.w, a1.x, a1.y, a1.z, a1.w};
            float b[8] = {b0.x, b0.y, b0.z, b0.w, b1.x, b1.y, b1.z, b1.w};
#pragma unroll
            for (int i = 0; i < 8; i++)
#pragma unroll
                for (int j = 0; j < 8; j++) acc[i][j] += a[i] * b[j];
        }
        if (more) {
            buf ^= 1;
            PROJ_STORE(buf);
            __syncthreads();
        }
    }

#pragma unroll
    for (int i = 0; i < 8; i++) {
        const int m = m0 + ((i < 4) ? ty * 4 + i : 64 + ty * 4 + (i - 4));
#pragma unroll
        for (int jh = 0; jh < 2; jh++) {
            const int n = n0 + jh * 64 + tx * 4;
            float4 r;
            r.x = acc[i][jh * 4 + 0] + bias[n + 0];
            r.y = acc[i][jh * 4 + 1] + bias[n + 1];
            r.z = acc[i][jh * 4 + 2] + bias[n + 2];
            r.w = acc[i][jh * 4 + 3] + bias[n + 3];
            *(float4*)(Cm + (size_t)m * D + n) = r;
        }
    }
#undef PROJ_LOAD
#undef PROJ_STORE
}

// ============================================================
// scores: merged A/B/C head-batched GEMMs (K=64), 64x64 tile,
// with dead-tile pruning for B and C.
//   bi <  64 : Sa[h,i,j] = q_h . k_h
//   bi < 192 : Sb[h,i,e] = q_h . rkt_h   (live iff 386<=m0+n0<=1023)
//   else     : Sc[h,e,j] = rqt_h . k_h   (live iff 0<=m0-n0<=512)
// ============================================================
__global__ __launch_bounds__(256) void scores_kernel(
        const float* __restrict__ qf, const float* __restrict__ kf,
        const float* __restrict__ rkt, const float* __restrict__ rqt,
        float* __restrict__ Sa, float* __restrict__ Sb, float* __restrict__ Sc) {
    const int h = blockIdx.y;
    int bi = blockIdx.x;
    const float *A, *B; float* Cm; int m0, n0, ldc;

    if (bi < 64) {
        m0 = (bi >> 3) * 64; n0 = (bi & 7) * 64;
        A = qf; B = kf; Cm = Sa + (size_t)h * S * S; ldc = S;
    } else if (bi < 192) {
        bi -= 64;
        m0 = (bi >> 4) * 64; n0 = (bi & 15) * 64;
        const int sum = m0 + n0;                 // j = e+i-512
        if (sum + 126 < 512 || sum > 1023) return;
        A = qf; B = rkt; Cm = Sb + (size_t)h * S * NE; ldc = NE;
    } else {
        bi -= 192;
        m0 = (bi >> 3) * 64; n0 = (bi & 7) * 64; // rows e, cols j; i = j-e+512
        const int d = m0 - n0;
        if (d < 0 || d > 512) return;
        A = rqt; B = kf; Cm = Sc + (size_t)h * NE * S; ldc = S;
    }
    A += h * HD; B += h * HD;   // head slice, lda = ldb = D

    __shared__ float As[16][64];
    __shared__ float Bs[16][64];
    const int tid = threadIdx.x;
    const int tx = tid & 15, ty = tid >> 4;
    const int lm = tid >> 2;
    const int lk = (tid & 3) * 4;

    float acc[4][4];
#pragma unroll
    for (int i = 0; i < 4; i++)
#pragma unroll
        for (int j = 0; j < 4; j++) acc[i][j] = 0.f;

    for (int k0 = 0; k0 < HD; k0 += 16) {
        float4 av = *(const float4*)(A + (size_t)(m0 + lm) * D + k0 + lk);
        float4 bv = *(const float4*)(B + (size_t)(n0 + lm) * D + k0 + lk);
        As[lk + 0][lm] = av.x; As[lk + 1][lm] = av.y;
        As[lk + 2][lm] = av.z; As[lk + 3][lm] = av.w;
        Bs[lk + 0][lm] = bv.x; Bs[lk + 1][lm] = bv.y;
        Bs[lk + 2][lm] = bv.z; Bs[lk + 3][lm] = bv.w;
        __syncthreads();
#pragma unroll
        for (int kk = 0; kk < 16; kk++) {
            float a[4], b[4];
#pragma unroll
            for (int i = 0; i < 4; i++) a[i] = As[kk][ty + 16 * i];
#pragma unroll
            for (int j = 0; j < 4; j++) b[j] = Bs[kk][tx + 16 * j];
#pragma unroll
            for (int i = 0; i < 4; i++)
#pragma unroll
                for (int j = 0; j < 4; j++) acc[i][j] += a[i] * b[j];
        }
        __syncthreads();
    }

#pragma unroll
    for (int i = 0; i < 4; i++) {
        const int m = m0 + ty + 16 * i;
#pragma unroll
        for (int j = 0; j < 4; j++) {
            const int n = n0 + tx + 16 * j;
            Cm[(size_t)m * ldc + n] = acc[i][j];
        }
    }
}

// ============================================================
// softmax over j with diagonal gather of Sb/Sc.
// ============================================================
__global__ void softmax_gather_kernel(const float* __restrict__ Asc,
                                      const float* __restrict__ Bm,
                                      const float* __restrict__ Cmat,
                                      float* __restrict__ attn) {
    const int i = blockIdx.x, h = blockIdx.y;
    const int j = threadIdx.x;
    const int e = j - i + NE / 2;   // [1, 1023]

    __shared__ float red[16];
    __shared__ float bc;

    float sc = (Asc[((size_t)h * S + i) * S + j]
              + Bm[((size_t)h * S + i) * NE + e]
              + Cmat[((size_t)h * NE + e) * S + j]) * 0.125f;

    const int warp = j >> 5, lane = j & 31;

    float vmax = sc;
#pragma unroll
    for (int o = 16; o; o >>= 1) vmax = fmaxf(vmax, __shfl_xor_sync(0xffffffffu, vmax, o));
    if (lane == 0) red[warp] = vmax;
    __syncthreads();
    if (warp == 0) {
        float w = (lane < 16) ? red[lane] : -1e30f;
#pragma unroll
        for (int o = 8; o; o >>= 1) w = fmaxf(w, __shfl_xor_sync(0xffffffffu, w, o));
        if (lane == 0) bc = w;
    }
    __syncthreads();
    const float ex = __expf(sc - bc);

    float vsum = ex;
#pragma unroll
    for (int o = 16; o; o >>= 1) vsum += __shfl_xor_sync(0xffffffffu, vsum, o);
    if (lane == 0) red[warp] = vsum;
    __syncthreads();
    if (warp == 0) {
        float w = (lane < 16) ? red[lane] : 0.f;
#pragma unroll
        for (int o = 8; o; o >>= 1) w += __shfl_xor_sync(0xffffffffu, w, o);
        if (lane == 0) bc = w;
    }
    __syncthreads();

    attn[((size_t)h * S + i) * S + j] = ex / bc;
}

// ============================================================
// small-tile GEMM (32x64), for ctx (B in [K,N]) and out (B in [N,K]).
// ============================================================
template <bool B_NK>
__global__ __launch_bounds__(256) void gemm_small_kernel(
        const float* __restrict__ A, int lda, int aOff,
        const float* __restrict__ B, int ldb, int bOff,
        const float* __restrict__ bias,
        float* __restrict__ Cm, int ldc, int cOff, int K) {
    const int z = blockIdx.z;
    A += (size_t)z * aOff; B += (size_t)z * bOff; Cm += (size_t)z * cOff;

    const int m0 = blockIdx.y * 32, n0 = blockIdx.x * 64;

    __shared__ float As[16][33];
    __shared__ float Bs[16][68];

    const int tid = threadIdx.x;
    const int tx = tid & 15, ty = tid >> 4;
    const int rm = tid >> 3, kc2 = (tid & 7) * 2;      // A loader
    const int rn = tid >> 2, kc4 = (tid & 3) * 4;      // B loader (NK)
    const int rk = tid >> 4, nc4 = (tid & 15) * 4;     // B loader (KN)

    float acc[2][4];
#pragma unroll
    for (int i = 0; i < 2; i++)
#pragma unroll
        for (int j = 0; j < 4; j++) acc[i][j] = 0.f;

    for (int k0 = 0; k0 < K; k0 += 16) {
        float2 av = *(const float2*)(A + (size_t)(m0 + rm) * lda + k0 + kc2);
        As[kc2 + 0][rm] = av.x;
        As[kc2 + 1][rm] = av.y;
        if (B_NK) {
            float4 bv = *(const float4*)(B + (size_t)(n0 + rn) * ldb + k0 + kc4);
            Bs[kc4 + 0][rn] = bv.x; Bs[kc4 + 1][rn] = bv.y;
            Bs[kc4 + 2][rn] = bv.z; Bs[kc4 + 3][rn] = bv.w;
        } else {
            float4 bv = *(const float4*)(B + (size_t)(k0 + rk) * ldb + n0 + nc4);
            *(float4*)&Bs[rk][nc4] = bv;
        }
        __syncthreads();
#pragma unroll
        for (int kk = 0; kk < 16; kk++) {
            float a[2], b[4];
            a[0] = As[kk][ty]; a[1] = As[kk][16 + ty];
#pragma unroll
            for (int j = 0; j < 4; j++) b[j] = Bs[kk][tx + 16 * j];
#pragma unroll
            for (int i = 0; i < 2; i++)
#pragma unroll
                for (int j = 0; j < 4; j++) acc[i][j] += a[i] * b[j];
        }
        __syncthreads();
    }

#pragma unroll
    for (int i = 0; i < 2; i++) {
        const int m = m0 + ty + 16 * i;
#pragma unroll
        for (int j = 0; j < 4; j++) {
            const int n = n0 + tx + 16 * j;
            float r = acc[i][j];
            if (bias) r += bias[n];
            Cm[(size_t)m * ldc + n] = r;
        }
    }
}

extern "C" void kernel_launch(void* const* d_in, const int* in_sizes, int n_in,
                              void* d_out, int out_size) {
    const float* hs  = (const float*)d_in[0];
    const float* emb = (const float*)d_in[1];
    const float* wq  = (const float*)d_in[2];
    const float* bq  = (const float*)d_in[3];
    const float* wk  = (const float*)d_in[4];
    const float* bk  = (const float*)d_in[5];
    const float* wv  = (const float*)d_in[6];
    const float* bv  = (const float*)d_in[7];
    const float* wrk = (const float*)d_in[8];
    const float* brk = (const float*)d_in[9];
    const float* wrq = (const float*)d_in[10];
    const float* brq = (const float*)d_in[11];
    const float* wo  = (const float*)d_in[12];
    const float* bo  = (const float*)d_in[13];

    float* out  = (float*)d_out;          // [1,512,512]
    float* attn = out + (size_t)S * D;    // [1,8,512,512]

    float *q, *k, *v, *rkt, *rqt, *ctx, *Asc, *Bm, *Cm;
    cudaGetSymbolAddress((void**)&q,   g_q);
    cudaGetSymbolAddress((void**)&k,   g_k);
    cudaGetSymbolAddress((void**)&v,   g_v);
    cudaGetSymbolAddress((void**)&rkt, g_rkt);
    cudaGetSymbolAddress((void**)&rqt, g_rqt);
    cudaGetSymbolAddress((void**)&ctx, g_ctx);
    cudaGetSymbolAddress((void**)&Asc, g_A);
    cudaGetSymbolAddress((void**)&Bm,  g_B);
    cudaGetSymbolAddress((void**)&Cm,  g_C);

    // 1. fused projections (112 live blocks of 256 thr)
    proj_kernel<<<dim3(4, 8, 5), 256>>>(hs, emb, wq, bq, wk, bk, wv, bv,
                                        wrk, brk, wrq, brq, q, k, v, rkt, rqt);

    // 2. all score GEMMs, one launch (64+128+128 tiles x 8 heads, pruned)
    scores_kernel<<<dim3(320, H), 256>>>(q, k, rkt, rqt, Asc, Bm, Cm);

    // 3. gather + softmax -> attn (in d_out)
    softmax_gather_kernel<<<dim3(S, H), S>>>(Asc, Bm, Cm, attn);

    // 4. ctx_h = attn_h @ v_h   (128 blocks)
    gemm_small_kernel<false><<<dim3(1, 16, H), 256>>>(
        attn, S, S * S, v, D, HD, nullptr, ctx, D, HD, S);

    // 5. out = ctx @ wo^T + bo  (128 blocks)
    gemm_small_kernel<true><<<dim3(8, 16, 1), 256>>>(
        ctx, D, 0, wo, D, 0, bo, out, D, 0, D);
}